// round 13
// baseline (speedup 1.0000x reference)
#include <cuda_runtime.h>
#include <cstdint>

// Problem constants
#define TT   100
#define BB   256
#define NIN  1024
#define NHID 4096
#define NOUT 512

#define BETA   0.95f
#define THRESH 1.0f

// Confirmed reference arithmetic: cuBLASLt serial split-K.
#define SPLIT1 2
#define SPLIT2 16

// Scratch (allocation-free rule: __device__ globals)
__device__ float g_spk1[(size_t)TT * BB * NHID];        // 419 MB
__device__ float g_part[(size_t)16 * TT * BB * NOUT];   // 839 MB

// ---------------------------------------------------------------------------
// Packed fp32 FMA: two independent IEEE fp32 RN FMAs per instruction.
// ---------------------------------------------------------------------------
__device__ __forceinline__ void fma_f32x2(unsigned long long& acc,
                                          unsigned long long a2,
                                          unsigned long long b2) {
    asm("fma.rn.f32x2 %0, %1, %2, %0;" : "+l"(acc) : "l"(a2), "l"(b2));
}
__device__ __forceinline__ unsigned long long pack_dup(float x) {
    unsigned long long r;
    asm("mov.b64 %0, {%1, %1};" : "=l"(r) : "f"(x));
    return r;
}
__device__ __forceinline__ void unpack2(unsigned long long v, float& lo, float& hi) {
    asm("mov.b64 {%0, %1}, %2;" : "=f"(lo), "=f"(hi) : "l"(v));
}

// ---------------------------------------------------------------------------
// Partial SGEMM (NT): Part[s][M][N] = A[M, ks..ks+Kc) @ B[N, ks..ks+Kc)^T
// BM=256 x BN=128 tile, BK=16, 256 threads, 16x8 micro-tile per thread.
// FFMA2 pairs ROWS. A lane-pairs come straight from LDS.128 register quads.
// B is stored DUPLICATED in smem (each value twice, b64-aligned), so B
// dup-lanes ALSO come straight from LDS.128 — zero packing MOVs in the loop.
// A smem: per-16-row 4-word pad (LDA=324) -> conflict-free A frag loads.
// B smem: word(n) = 2n + ((n>>3)<<2), row stride 324 -> conflict-free frags.
// NUMERICS: per output element, one fp32 accumulator lane folded by an
// ascending-k FMA chain from 0 — bitwise identical to the passing kernel.
// ---------------------------------------------------------------------------
#define BM 256
#define BN 128
#define BK 16
#define LDA 324
#define LDBD 324                      // duplicated-B row stride (words)
#define ABUF ((size_t)BK * LDA)
#define BBUF ((size_t)BK * LDBD)
#define GEMM_SMEM ((size_t)2 * (ABUF + BBUF) * sizeof(float))

#define AIDX(k, m) ((k) * LDA + (m) + (((m) >> 4) << 2))
#define BWORD(n)   (2 * (n) + (((n) >> 3) << 2))   // dup-pair word offset

__global__ __launch_bounds__(256, 1)
void sgemm_nt_part(const float* __restrict__ A,
                   const float* __restrict__ Bm,
                   float* __restrict__ Part,
                   int M, int N, int K, int Kc)
{
    extern __shared__ float sm[];
    float* Abase = sm;                        // 2 buffers of BK*LDA
    float* Bbase = sm + 2 * ABUF;             // 2 buffers of BK*LDBD (dup)

    const int tid  = threadIdx.x;
    const int bm   = blockIdx.y * BM;
    const int bn   = blockIdx.x * BN;
    const int s    = blockIdx.z;
    const int kb   = s * Kc;

    const int warp = tid >> 5;
    const int lane = tid & 31;
    const int m0 = (warp & 1) * 128 + (lane >> 2) * 16;
    const int n0 = (warp >> 1) * 32 + (lane & 3) * 8;
    const int mpad = m0 + ((m0 >> 4) << 2);
    const int bw   = BWORD(n0);               // B frag base word

    const int lr = tid >> 2;          // base row 0..63
    const int c4 = (tid & 3) * 4;     // k-offset 0,4,8,12

    const float* Ap = A  + (size_t)bm * K + kb;
    const float* Bp = Bm + (size_t)bn * K + kb;

    // Packed accumulators: accp[i2][j] lanes = rows (m0+2*i2, m0+2*i2+1), col j.
    unsigned long long accp[8][8];
#pragma unroll
    for (int i = 0; i < 8; i++)
#pragma unroll
        for (int j = 0; j < 8; j++) accp[i][j] = 0ull;

    const int NT = Kc / BK;
    float4 ar[4], br[2];

    // ---- prologue: global tile 0 -> smem buffer 0 ----
#pragma unroll
    for (int i = 0; i < 4; i++)
        ar[i] = *(const float4*)(Ap + (size_t)(lr + i * 64) * K + c4);
#pragma unroll
    for (int i = 0; i < 2; i++)
        br[i] = *(const float4*)(Bp + (size_t)(lr + i * 64) * K + c4);
#pragma unroll
    for (int i = 0; i < 4; i++) {
        const int r = lr + i * 64;
        Abase[AIDX(c4 + 0, r)] = ar[i].x; Abase[AIDX(c4 + 1, r)] = ar[i].y;
        Abase[AIDX(c4 + 2, r)] = ar[i].z; Abase[AIDX(c4 + 3, r)] = ar[i].w;
    }
#pragma unroll
    for (int i = 0; i < 2; i++) {
        const int r = lr + i * 64;
        const int w = BWORD(r);
        const float v[4] = { br[i].x, br[i].y, br[i].z, br[i].w };
#pragma unroll
        for (int j = 0; j < 4; j++)
            *(unsigned long long*)&Bbase[(size_t)(c4 + j) * LDBD + w] = pack_dup(v[j]);
    }
    __syncthreads();

    for (int kt = 0; kt < NT; kt++) {
        const int cur = kt & 1;
        const float* Ab = Abase + cur * ABUF;
        const float* Bb = Bbase + cur * BBUF;

        // prefetch next global tile into registers (LDG hidden under compute)
        if (kt + 1 < NT) {
            const int k0 = (kt + 1) * BK;
#pragma unroll
            for (int i = 0; i < 4; i++)
                ar[i] = *(const float4*)(Ap + (size_t)(lr + i * 64) * K + k0 + c4);
#pragma unroll
            for (int i = 0; i < 2; i++)
                br[i] = *(const float4*)(Bp + (size_t)(lr + i * 64) * K + k0 + c4);
        }

        // compute: ascending k within the tile (per-lane chain order preserved)
#pragma unroll
        for (int k = 0; k < BK; k++) {
            union { float4 f; unsigned long long u[2]; } av[4], bv[4];
#pragma unroll
            for (int i = 0; i < 4; i++)
                av[i].f = *(const float4*)&Ab[k * LDA + mpad + 4 * i];
#pragma unroll
            for (int j = 0; j < 4; j++)
                bv[j].f = *(const float4*)&Bb[k * LDBD + bw + 4 * j];
            // bv[j].u[0] = dup(b[n0+2j]), bv[j].u[1] = dup(b[n0+2j+1])

#pragma unroll
            for (int i2 = 0; i2 < 8; i2++) {
                const unsigned long long a2 = av[i2 >> 1].u[i2 & 1];
#pragma unroll
                for (int j = 0; j < 8; j++)
                    fma_f32x2(accp[i2][j], a2, bv[j >> 1].u[j & 1]);
            }
        }

        if (kt + 1 < NT) {
            float* An = Abase + (cur ^ 1) * ABUF;
            float* Bn = Bbase + (cur ^ 1) * BBUF;
#pragma unroll
            for (int i = 0; i < 4; i++) {
                const int r = lr + i * 64;
                An[AIDX(c4 + 0, r)] = ar[i].x; An[AIDX(c4 + 1, r)] = ar[i].y;
                An[AIDX(c4 + 2, r)] = ar[i].z; An[AIDX(c4 + 3, r)] = ar[i].w;
            }
#pragma unroll
            for (int i = 0; i < 2; i++) {
                const int r = lr + i * 64;
                const int w = BWORD(r);
                const float v[4] = { br[i].x, br[i].y, br[i].z, br[i].w };
#pragma unroll
                for (int j = 0; j < 4; j++)
                    *(unsigned long long*)&Bn[(size_t)(c4 + j) * LDBD + w] = pack_dup(v[j]);
            }
            __syncthreads();
        }
    }

    // epilogue: unpack row-pairs; store raw partials (reduce+bias in LIF)
    float* base = Part + (size_t)s * M * N + (size_t)(bm + m0) * N + bn + n0;
#pragma unroll
    for (int i2 = 0; i2 < 8; i2++) {
        float lo[8], hi[8];
#pragma unroll
        for (int j = 0; j < 8; j++)
            unpack2(accp[i2][j], lo[j], hi[j]);
        float* r0 = base + (size_t)(2 * i2) * N;
        float* r1 = base + (size_t)(2 * i2 + 1) * N;
        *(float4*)(r0)     = make_float4(lo[0], lo[1], lo[2], lo[3]);
        *(float4*)(r0 + 4) = make_float4(lo[4], lo[5], lo[6], lo[7]);
        *(float4*)(r1)     = make_float4(hi[0], hi[1], hi[2], hi[3]);
        *(float4*)(r1 + 4) = make_float4(hi[4], hi[5], hi[6], hi[7]);
    }
}

// ---------------------------------------------------------------------------
// LIF scans with fused split-K reduce + bias (rounding sequence unchanged).
// ---------------------------------------------------------------------------
__global__ void lif_scan1(const float* __restrict__ part,
                          const float* __restrict__ bias,
                          float* __restrict__ spk1)
{
    const int idx = blockIdx.x * blockDim.x + threadIdx.x;
    if (idx >= BB * NHID) return;
    const size_t stride  = (size_t)BB * NHID;
    const size_t pstride = (size_t)TT * BB * NHID;
    const float  bv = bias[idx % NHID];
    size_t off = idx;
    float mem = 0.0f;
#pragma unroll 4
    for (int t = 0; t < TT; t++) {
        float c = __fadd_rn(part[off], part[pstride + off]);
        c = __fadd_rn(c, bv);
        const float rst = (mem > THRESH) ? THRESH : 0.0f;
        float u = __fmul_rn(BETA, mem);
        u = __fadd_rn(u, c);
        mem = __fsub_rn(u, rst);
        spk1[off] = (mem > THRESH) ? 1.0f : 0.0f;
        off += stride;
    }
}

__global__ void lif_scan2(const float* __restrict__ part,
                          const float* __restrict__ bias,
                          float* __restrict__ out)
{
    const int idx = blockIdx.x * blockDim.x + threadIdx.x;
    if (idx >= BB * NOUT) return;
    const size_t stride  = (size_t)BB * NOUT;
    const size_t pstride = (size_t)TT * BB * NOUT;
    const size_t half    = (size_t)TT * BB * NOUT;
    const float  bv = bias[idx % NOUT];
    size_t off = idx;
    float mem = 0.0f;
    for (int t = 0; t < TT; t++) {
        float c = part[off];
#pragma unroll
        for (int s = 1; s < SPLIT2; s++)
            c = __fadd_rn(c, part[(size_t)s * pstride + off]);
        c = __fadd_rn(c, bv);
        const float rst = (mem > THRESH) ? THRESH : 0.0f;
        float u = __fmul_rn(BETA, mem);
        u = __fadd_rn(u, c);
        mem = __fsub_rn(u, rst);
        out[off]        = (mem > THRESH) ? 1.0f : 0.0f;  // spk_rec
        out[half + off] = mem;                           // mem_rec
        off += stride;
    }
}

// ---------------------------------------------------------------------------
// Launch
// ---------------------------------------------------------------------------
extern "C" void kernel_launch(void* const* d_in, const int* in_sizes, int n_in,
                              void* d_out, int out_size)
{
    const float* x  = (const float*)d_in[0];   // [T,B,NIN]
    const float* W1 = (const float*)d_in[1];   // [NHID,NIN]
    const float* b1 = (const float*)d_in[2];   // [NHID]
    const float* W2 = (const float*)d_in[3];   // [NOUT,NHID]
    const float* b2 = (const float*)d_in[4];   // [NOUT]
    float* out = (float*)d_out;

    float* spk1; cudaGetSymbolAddress((void**)&spk1, g_spk1);
    float* part; cudaGetSymbolAddress((void**)&part, g_part);

    cudaFuncSetAttribute(sgemm_nt_part,
                         cudaFuncAttributeMaxDynamicSharedMemorySize,
                         (int)GEMM_SMEM);

    const int M = TT * BB;  // 25600

    // GEMM1 partials: split-K = 2 over K=1024
    {
        dim3 grid(NHID / BN, M / BM, SPLIT1);
        sgemm_nt_part<<<grid, 256, GEMM_SMEM>>>(x, W1, part, M, NHID, NIN, NIN / SPLIT1);
    }

    // LIF scan layer 1 (fused split-K reduce + bias) -> spike train
    {
        const int n = BB * NHID;
        lif_scan1<<<(n + 255) / 256, 256>>>(part, b1, spk1);
    }

    // GEMM2 partials: split-K = 16 over K=4096
    {
        dim3 grid(NOUT / BN, M / BM, SPLIT2);
        sgemm_nt_part<<<grid, 256, GEMM_SMEM>>>(spk1, W2, part, M, NOUT, NHID, NHID / SPLIT2);
    }

    // LIF scan layer 2 (fused reduce + bias) -> d_out (spk_rec || mem_rec)
    {
        const int n = BB * NOUT;
        lif_scan2<<<(n + 255) / 256, 256>>>(part, b2, out);
    }
}

// round 16
// speedup vs baseline: 1.0590x; 1.0590x over previous
#include <cuda_runtime.h>
#include <cstdint>

// Problem constants
#define TT   100
#define BB   256
#define NIN  1024
#define NHID 4096
#define NOUT 512

#define BETA   0.95f
#define THRESH 1.0f

// Confirmed reference arithmetic: cuBLASLt serial split-K.
#define SPLIT1 2
#define SPLIT2 16

// Scratch (allocation-free rule: __device__ globals)
__device__ float g_spk1[(size_t)TT * BB * NHID];        // 419 MB
__device__ float g_part[(size_t)16 * TT * BB * NOUT];   // 839 MB

// ---------------------------------------------------------------------------
// Packed fp32 FMA: two independent IEEE fp32 RN FMAs per instruction.
// ---------------------------------------------------------------------------
__device__ __forceinline__ void fma_f32x2(unsigned long long& acc,
                                          unsigned long long a2,
                                          unsigned long long b2) {
    asm("fma.rn.f32x2 %0, %1, %2, %0;" : "+l"(acc) : "l"(a2), "l"(b2));
}
__device__ __forceinline__ unsigned long long pack_dup(float x) {
    unsigned long long r;
    asm("mov.b64 %0, {%1, %1};" : "=l"(r) : "f"(x));
    return r;
}
__device__ __forceinline__ void unpack2(unsigned long long v, float& lo, float& hi) {
    asm("mov.b64 {%0, %1}, %2;" : "=f"(lo), "=f"(hi) : "l"(v));
}

// ---------------------------------------------------------------------------
// Partial SGEMM (NT): Part[s][M][N] = A[M, ks..ks+Kc) @ B[N, ks..ks+Kc)^T
// BM=256 x BN=128 tile, BK=32 (halved barrier count vs BK=16), 256 threads,
// 16x8 micro-tile. FFMA2 pairs ROWS: A lane-pairs come straight from the
// LDS.128 register quads (round-12 structure, unchanged hot loop).
// A smem: per-16-row 4-word pad (LDA=324) -> conflict-free A frag loads.
// NUMERICS: per output element, one fp32 accumulator lane folded by an
// ascending-k FMA chain from 0 — bitwise identical to the passing kernel.
// ---------------------------------------------------------------------------
#define BM 256
#define BN 128
#define BK 32
#define LDA 324
#define LDB (BN + 4)
#define ABUF ((size_t)BK * LDA)
#define BBUF ((size_t)BK * LDB)
#define GEMM_SMEM ((size_t)2 * (ABUF + BBUF) * sizeof(float))

#define AIDX(k, m) ((k) * LDA + (m) + (((m) >> 4) << 2))

__global__ __launch_bounds__(256, 1)
void sgemm_nt_part(const float* __restrict__ A,
                   const float* __restrict__ Bm,
                   float* __restrict__ Part,
                   int M, int N, int K, int Kc)
{
    extern __shared__ float sm[];
    float* Abase = sm;                       // 2 buffers of BK*LDA
    float (*Bs)[BK][LDB] = (float (*)[BK][LDB])(sm + 2 * ABUF);

    const int tid  = threadIdx.x;
    const int bm   = blockIdx.y * BM;
    const int bn   = blockIdx.x * BN;
    const int s    = blockIdx.z;
    const int kb   = s * Kc;

    const int warp = tid >> 5;
    const int lane = tid & 31;
    const int m0 = (warp & 1) * 128 + (lane >> 2) * 16;
    const int n0 = (warp >> 1) * 32 + (lane & 3) * 8;
    const int mpad = m0 + ((m0 >> 4) << 2);

    const int lr = tid >> 2;          // base row 0..63
    const int c4 = (tid & 3) * 4;     // k-offset 0,4,8,12 (+16 for 2nd half)

    const float* Ap = A  + (size_t)bm * K + kb;
    const float* Bp = Bm + (size_t)bn * K + kb;

    // Packed accumulators: accp[i2][j] lanes = rows (m0+2*i2, m0+2*i2+1), col j.
    unsigned long long accp[8][8];
#pragma unroll
    for (int i = 0; i < 8; i++)
#pragma unroll
        for (int j = 0; j < 8; j++) accp[i][j] = 0ull;

    const int NT = Kc / BK;
    float4 ar[8], br[4];   // staging: rows x 2 k-halves

    // ---- prologue: global tile 0 -> smem buffer 0 ----
#pragma unroll
    for (int h = 0; h < 2; h++) {
        const int kofs = c4 + 16 * h;
#pragma unroll
        for (int i = 0; i < 4; i++)
            ar[h * 4 + i] = *(const float4*)(Ap + (size_t)(lr + i * 64) * K + kofs);
#pragma unroll
        for (int i = 0; i < 2; i++)
            br[h * 2 + i] = *(const float4*)(Bp + (size_t)(lr + i * 64) * K + kofs);
    }
#pragma unroll
    for (int h = 0; h < 2; h++) {
        const int kofs = c4 + 16 * h;
#pragma unroll
        for (int i = 0; i < 4; i++) {
            const int r = lr + i * 64;
            const float4 v = ar[h * 4 + i];
            Abase[AIDX(kofs + 0, r)] = v.x; Abase[AIDX(kofs + 1, r)] = v.y;
            Abase[AIDX(kofs + 2, r)] = v.z; Abase[AIDX(kofs + 3, r)] = v.w;
        }
#pragma unroll
        for (int i = 0; i < 2; i++) {
            const int r = lr + i * 64;
            const float4 v = br[h * 2 + i];
            Bs[0][kofs + 0][r] = v.x; Bs[0][kofs + 1][r] = v.y;
            Bs[0][kofs + 2][r] = v.z; Bs[0][kofs + 3][r] = v.w;
        }
    }
    __syncthreads();

    for (int kt = 0; kt < NT; kt++) {
        const int cur = kt & 1;
        const float* Ab = Abase + cur * ABUF;

        // prefetch next global tile into registers (LDG hidden under compute)
        if (kt + 1 < NT) {
            const int k0 = (kt + 1) * BK;
#pragma unroll
            for (int h = 0; h < 2; h++) {
                const int kofs = k0 + c4 + 16 * h;
#pragma unroll
                for (int i = 0; i < 4; i++)
                    ar[h * 4 + i] = *(const float4*)(Ap + (size_t)(lr + i * 64) * K + kofs);
#pragma unroll
                for (int i = 0; i < 2; i++)
                    br[h * 2 + i] = *(const float4*)(Bp + (size_t)(lr + i * 64) * K + kofs);
            }
        }

        // compute: ascending k within the tile (per-lane chain order preserved)
#pragma unroll
        for (int k = 0; k < BK; k++) {
            union { float4 f; unsigned long long u[2]; } av[4];
#pragma unroll
            for (int i = 0; i < 4; i++)
                av[i].f = *(const float4*)&Ab[k * LDA + mpad + 4 * i];

            float b[8];
            *(float4*)(b)     = *(const float4*)&Bs[cur][k][n0];
            *(float4*)(b + 4) = *(const float4*)&Bs[cur][k][n0 + 4];
            unsigned long long bd[8];
#pragma unroll
            for (int j = 0; j < 8; j++)
                bd[j] = pack_dup(b[j]);

#pragma unroll
            for (int i2 = 0; i2 < 8; i2++) {
                const unsigned long long a2 = av[i2 >> 1].u[i2 & 1];
#pragma unroll
                for (int j = 0; j < 8; j++)
                    fma_f32x2(accp[i2][j], a2, bd[j]);
            }
        }

        if (kt + 1 < NT) {
            float* An = Abase + (cur ^ 1) * ABUF;
            const int nxt = cur ^ 1;
#pragma unroll
            for (int h = 0; h < 2; h++) {
                const int kofs = c4 + 16 * h;
#pragma unroll
                for (int i = 0; i < 4; i++) {
                    const int r = lr + i * 64;
                    const float4 v = ar[h * 4 + i];
                    An[AIDX(kofs + 0, r)] = v.x; An[AIDX(kofs + 1, r)] = v.y;
                    An[AIDX(kofs + 2, r)] = v.z; An[AIDX(kofs + 3, r)] = v.w;
                }
#pragma unroll
                for (int i = 0; i < 2; i++) {
                    const int r = lr + i * 64;
                    const float4 v = br[h * 2 + i];
                    Bs[nxt][kofs + 0][r] = v.x; Bs[nxt][kofs + 1][r] = v.y;
                    Bs[nxt][kofs + 2][r] = v.z; Bs[nxt][kofs + 3][r] = v.w;
                }
            }
            __syncthreads();
        }
    }

    // epilogue: unpack row-pairs; store raw partials (reduce+bias in LIF)
    float* base = Part + (size_t)s * M * N + (size_t)(bm + m0) * N + bn + n0;
#pragma unroll
    for (int i2 = 0; i2 < 8; i2++) {
        float lo[8], hi[8];
#pragma unroll
        for (int j = 0; j < 8; j++)
            unpack2(accp[i2][j], lo[j], hi[j]);
        float* r0 = base + (size_t)(2 * i2) * N;
        float* r1 = base + (size_t)(2 * i2 + 1) * N;
        *(float4*)(r0)     = make_float4(lo[0], lo[1], lo[2], lo[3]);
        *(float4*)(r0 + 4) = make_float4(lo[4], lo[5], lo[6], lo[7]);
        *(float4*)(r1)     = make_float4(hi[0], hi[1], hi[2], hi[3]);
        *(float4*)(r1 + 4) = make_float4(hi[4], hi[5], hi[6], hi[7]);
    }
}

// ---------------------------------------------------------------------------
// LIF scans with fused split-K reduce + bias (rounding sequence unchanged).
// ---------------------------------------------------------------------------
__global__ void lif_scan1(const float* __restrict__ part,
                          const float* __restrict__ bias,
                          float* __restrict__ spk1)
{
    const int idx = blockIdx.x * blockDim.x + threadIdx.x;
    if (idx >= BB * NHID) return;
    const size_t stride  = (size_t)BB * NHID;
    const size_t pstride = (size_t)TT * BB * NHID;
    const float  bv = bias[idx % NHID];
    size_t off = idx;
    float mem = 0.0f;
#pragma unroll 4
    for (int t = 0; t < TT; t++) {
        float c = __fadd_rn(part[off], part[pstride + off]);
        c = __fadd_rn(c, bv);
        const float rst = (mem > THRESH) ? THRESH : 0.0f;
        float u = __fmul_rn(BETA, mem);
        u = __fadd_rn(u, c);
        mem = __fsub_rn(u, rst);
        spk1[off] = (mem > THRESH) ? 1.0f : 0.0f;
        off += stride;
    }
}

__global__ void lif_scan2(const float* __restrict__ part,
                          const float* __restrict__ bias,
                          float* __restrict__ out)
{
    const int idx = blockIdx.x * blockDim.x + threadIdx.x;
    if (idx >= BB * NOUT) return;
    const size_t stride  = (size_t)BB * NOUT;
    const size_t pstride = (size_t)TT * BB * NOUT;
    const size_t half    = (size_t)TT * BB * NOUT;
    const float  bv = bias[idx % NOUT];
    size_t off = idx;
    float mem = 0.0f;
    for (int t = 0; t < TT; t++) {
        float c = part[off];
#pragma unroll
        for (int s = 1; s < SPLIT2; s++)
            c = __fadd_rn(c, part[(size_t)s * pstride + off]);
        c = __fadd_rn(c, bv);
        const float rst = (mem > THRESH) ? THRESH : 0.0f;
        float u = __fmul_rn(BETA, mem);
        u = __fadd_rn(u, c);
        mem = __fsub_rn(u, rst);
        out[off]        = (mem > THRESH) ? 1.0f : 0.0f;  // spk_rec
        out[half + off] = mem;                           // mem_rec
        off += stride;
    }
}

// ---------------------------------------------------------------------------
// Launch
// ---------------------------------------------------------------------------
extern "C" void kernel_launch(void* const* d_in, const int* in_sizes, int n_in,
                              void* d_out, int out_size)
{
    const float* x  = (const float*)d_in[0];   // [T,B,NIN]
    const float* W1 = (const float*)d_in[1];   // [NHID,NIN]
    const float* b1 = (const float*)d_in[2];   // [NHID]
    const float* W2 = (const float*)d_in[3];   // [NOUT,NHID]
    const float* b2 = (const float*)d_in[4];   // [NOUT]
    float* out = (float*)d_out;

    float* spk1; cudaGetSymbolAddress((void**)&spk1, g_spk1);
    float* part; cudaGetSymbolAddress((void**)&part, g_part);

    cudaFuncSetAttribute(sgemm_nt_part,
                         cudaFuncAttributeMaxDynamicSharedMemorySize,
                         (int)GEMM_SMEM);

    const int M = TT * BB;  // 25600

    // GEMM1 partials: split-K = 2 over K=1024 (Kc=512, 16 k-tiles of 32)
    {
        dim3 grid(NHID / BN, M / BM, SPLIT1);
        sgemm_nt_part<<<grid, 256, GEMM_SMEM>>>(x, W1, part, M, NHID, NIN, NIN / SPLIT1);
    }

    // LIF scan layer 1 (fused split-K reduce + bias) -> spike train
    {
        const int n = BB * NHID;
        lif_scan1<<<(n + 255) / 256, 256>>>(part, b1, spk1);
    }

    // GEMM2 partials: split-K = 16 over K=4096 (Kc=256, 8 k-tiles of 32)
    {
        dim3 grid(NOUT / BN, M / BM, SPLIT2);
        sgemm_nt_part<<<grid, 256, GEMM_SMEM>>>(spk1, W2, part, M, NOUT, NHID, NHID / SPLIT2);
    }

    // LIF scan layer 2 (fused reduce + bias) -> d_out (spk_rec || mem_rec)
    {
        const int n = BB * NOUT;
        lif_scan2<<<(n + 255) / 256, 256>>>(part, b2, out);
    }
}